// round 16
// baseline (speedup 1.0000x reference)
#include <cuda_runtime.h>
#include <cuda_fp16.h>

// SparseVolumeReconstructionLinear — GB300 sm_103a
#define BATCH   256
#define ISIZE   8
#define HW      80
#define PX      81
#define PTS     (161 * 81)      // 13041
#define BZM     167
#define BZ2     83
#define GX      84
#define GZSTRIDE (BZM * GX)     // 14028
#define GRID_ELEMS (BZM * BZM * GX)
#define MR2     6400
#define NWMAX   1250000
#define TABN    (BZM * BZM)     // 27889

// Scratch (allocation-free: __device__ globals).
__device__ __half2 g_wh[NWMAX * 8];   // fp16 weight rows, 32 B each
__device__ uint2   g_bp[NWMAX];       // bias pair {bh[j], bh[j+1]}, 8 B
__device__ uint2   g_tp[TABN];        // per (z,y): {packed(z,y), packed(z,y+1)}

__device__ __forceinline__ int grid_is64(const int* __restrict__ g)
{
    const int r = 83 * GZSTRIDE + 83 * GX;   // even interior offset
    return (__ldg(g + r + 1) == 0) ? 1 : 0;
}

__device__ __forceinline__ int tab_packed(const int* __restrict__ grid3d,
                                          int z, int y, int is64)
{
    const int zb = z - BZ2, yb = y - BZ2;
    const int rr = MR2 - zb * zb - yb * yb;
    if (rr < 0) return 0;
    int xm = (int)sqrtf((float)rr);
    while ((xm + 1) * (xm + 1) <= rr) ++xm;
    while (xm * xm > rr) --xm;
    const int lin0 = z * GZSTRIDE + y * GX;
    const int rs = __ldg(grid3d + (is64 ? 2 * lin0 : lin0));
    return (rs << 7) | (xm + 1);
}

// Prep: fp16 convert (4 thr/row) + bias pairs + table pairs.
// Source fp32 reads use __ldcs (evict-first) so the one-shot stream does not
// evict the hot fp16 tables the main kernel is about to gather from.
__global__ __launch_bounds__(256) void prep_kernel(
    const float4* __restrict__ w, const float2* __restrict__ bia,
    const int* __restrict__ grid3d, int nw)
{
    const long long t = (long long)blockIdx.x * 256 + threadIdx.x;
    const long long cvt_n = (long long)nw * 4;

    if (t < cvt_n) {
        const int r = (int)(t >> 2), part = (int)(t & 3);
        const float4 a = __ldcs(w + (size_t)r * 4 + part);
        const __half2 h0 = __floats2half2_rn(a.x, a.y);
        const __half2 h1 = __floats2half2_rn(a.z, a.w);
        uint2 v;
        v.x = *reinterpret_cast<const unsigned*>(&h0);
        v.y = *reinterpret_cast<const unsigned*>(&h1);
        *reinterpret_cast<uint2*>(&g_wh[(size_t)r * 8 + part * 2]) = v;
        if (part == 0) {
            const float2 b0 = __ldcs(bia + r);
            const __half2 hb0 = __floats2half2_rn(b0.x, b0.y);
            __half2 hb1 = __floats2half2_rn(0.f, 0.f);
            if (r + 1 < nw) {
                const float2 b1 = __ldcs(bia + r + 1);
                hb1 = __floats2half2_rn(b1.x, b1.y);
            }
            uint2 bp;
            bp.x = *reinterpret_cast<const unsigned*>(&hb0);
            bp.y = *reinterpret_cast<const unsigned*>(&hb1);
            g_bp[r] = bp;
        }
    } else if (t < cvt_n + TABN) {
        const int e = (int)(t - cvt_n);
        const int z = e / BZM, y = e % BZM;
        const int is64 = grid_is64(grid3d);
        uint2 tp;
        tp.x = (unsigned)tab_packed(grid3d, z, y, is64);
        tp.y = (y + 1 < BZM) ? (unsigned)tab_packed(grid3d, z, y + 1, is64) : 0u;
        g_tp[e] = tp;
    }
}

__global__ __launch_bounds__(256, 7) void svr_kernel(
    const float*  __restrict__ input,    // (256, 8)
    const int*    __restrict__ grid3d,   // int32 (or int64 LE)
    const float*  __restrict__ rot,      // (256, 3, 3)
    float2*       __restrict__ out)      // (256, 13041, 2)
{
    const int b    = blockIdx.y;
    const int q    = blockIdx.x * 256 + threadIdx.x;
    const int lane = threadIdx.x & 31;
    const unsigned FULL = 0xffffffffu;

    // ---- Owner role: 8 corner indices + weights (via dx-pair records) ------
    int   jc[8];
    float wt[8];
    float simag = 1.f;

    bool active = false;
    if (q < PTS) {
        const int xi2 = q % PX;           // 0..80
        const int iy  = q / PX - HW;      // -80..80
        if (xi2 * xi2 + iy * iy <= MR2) {
            active = true;
            const float* R = rot + b * 9;
            const float x = (float)xi2, y = (float)iy;
            float cx = R[0] * x + R[1] * y;
            float cy = R[3] * x + R[4] * y;
            float cz = R[6] * x + R[7] * y;
            if (cx < 0.f) { cx = -cx; cy = -cy; cz = -cz; simag = -1.f; }

            const float fx = floorf(cx), fy = floorf(cy), fz = floorf(cz);
            const int   ix = (int)fx,    iyc = (int)fy,   iz = (int)fz;
            const float tx = cx - fx,    ty = cy - fy,    tz = cz - fz;

            const float wxl0 = 1.f - tx, wxl1 = tx;
            const float wyl[2] = {1.f - ty, ty};
            const float wzl[2] = {1.f - tz, tz};

            const int is64 = grid_is64(grid3d);
            #pragma unroll
            for (int dz = 0; dz < 2; ++dz) {
                const int zc  = iz + dz + BZ2;
                const int yc0 = iyc + BZ2;
                const uint2 tp = __ldg(g_tp + zc * BZM + yc0);
                #pragma unroll
                for (int dy = 0; dy < 2; ++dy) {
                    const int cc  = dz * 4 + dy * 2;        // jc slots cc, cc+1
                    const int yc  = yc0 + dy;
                    const int ent = (int)(dy ? tp.y : tp.x);
                    const int xm1 = ent & 127;
                    const int rs  = ent >> 7;
                    int jj0, jj1;
                    if (ix + 1 < xm1) {               // both corners in-ball
                        jj0 = rs + ix;
                        jj1 = jj0 + 1;
                    } else {                          // rare: edge / margin / expansion
                        const int lin = zc * GZSTRIDE + yc * GX + ix;
                        if (ix < xm1) jj0 = rs + ix;
                        else jj0 = __ldg(grid3d + (is64 ? 2 * lin : lin));
                        jj1 = __ldg(grid3d + (is64 ? 2 * (lin + 1) : lin + 1));
                    }
                    jc[cc]     = jj0;
                    jc[cc + 1] = jj1;
                    const float wzy = wzl[dz] * wyl[dy];
                    wt[cc]     = wzy * wxl0;
                    wt[cc + 1] = wzy * wxl1;
                }
            }
        }
    }
    if (!active) {
        #pragma unroll
        for (int c = 0; c < 8; ++c) { jc[c] = -1; wt[c] = 0.f; }
    }

    // Owner-side bias (paired LDG.64 on the common path; fallback via g_bp.x).
    float br = 0.f, bi = 0.f;
    #pragma unroll
    for (int c = 0; c < 8; c += 2) {
        const int jj0 = jc[c], jj1 = jc[c + 1];
        if (jj0 >= 0 && jj1 == jj0 + 1) {
            const uint2 bp = __ldg(g_bp + jj0);
            const float2 b0 = __half22float2(*reinterpret_cast<const __half2*>(&bp.x));
            const float2 b1 = __half22float2(*reinterpret_cast<const __half2*>(&bp.y));
            br += wt[c] * b0.x + wt[c + 1] * b1.x;
            bi += wt[c] * b0.y + wt[c + 1] * b1.y;
        } else {
            if (jj0 >= 0) {
                const uint2 bp = __ldg(g_bp + jj0);
                const float2 b0 = __half22float2(*reinterpret_cast<const __half2*>(&bp.x));
                br += wt[c] * b0.x; bi += wt[c] * b0.y;
            }
            if (jj1 >= 0) {
                const uint2 bp = __ldg(g_bp + jj1);
                const float2 b1 = __half22float2(*reinterpret_cast<const __half2*>(&bp.x));
                br += wt[c + 1] * b1.x; bi += wt[c + 1] * b1.y;
            }
        }
    }

    // ---- Team role: 2 lanes/row (slot = feature half), 16 rows per LDG.128 -
    const float4 fv = __ldg(reinterpret_cast<const float4*>(input + b * ISIZE) + (lane & 1));
    __half2 fh0 = __floats2half2_rn(fv.x, fv.x);
    __half2 fh1 = __floats2half2_rn(fv.y, fv.y);
    __half2 fh2 = __floats2half2_rn(fv.z, fv.z);
    __half2 fh3 = __floats2half2_rn(fv.w, fv.w);
    const int slot = lane & 1;
    const int rsel = lane >> 1;                // 0..15

    const uint4* wh = reinterpret_cast<const uint4*>(g_wh);  // 2 uint4 per row

    float accr[2] = {0.f, 0.f};
    float acci[2] = {0.f, 0.f};

    // Two chunks of 4 corners: hoist 8 (j,w) distributions, then 8
    // unconditional LDG.128 + HFMA2 dots (MLP = 8 per chunk). Chunking keeps
    // the live (j,w) arrays at 16 regs so the kernel fits the 7-block bound.
    #pragma unroll
    for (int half = 0; half < 2; ++half) {
        int   jr8[8];
        float wr8[8];
        #pragma unroll
        for (int dc = 0; dc < 4; ++dc) {
            const int c = half * 4 + dc;
            #pragma unroll
            for (int sub = 0; sub < 2; ++sub) {
                const int k   = dc * 2 + sub;
                const int src = sub * 16 + rsel;
                const int   jr = __shfl_sync(FULL, jc[c], src);
                const float wr = __shfl_sync(FULL, wt[c], src);
                wr8[k] = (jr >= 0) ? wr : 0.f;   // invalid corner contributes 0
                jr8[k] = (jr >= 0) ? jr : 0;     // safe row for unconditional load
            }
        }
        #pragma unroll
        for (int k = 0; k < 8; ++k) {
            const uint4 wv = __ldg(wh + (size_t)jr8[k] * 2 + slot);
            const __half2* hp = reinterpret_cast<const __half2*>(&wv);
            __half2 acc = __hmul2(fh0, hp[0]);
            acc = __hfma2(fh1, hp[1], acc);
            acc = __hfma2(fh2, hp[2], acc);
            acc = __hfma2(fh3, hp[3], acc);
            const float2 d = __half22float2(acc);
            accr[k & 1] += wr8[k] * d.x;
            acci[k & 1] += wr8[k] * d.y;
        }
    }

    // Reduce each sub over its lane pair (feature halves).
    #pragma unroll
    for (int sub = 0; sub < 2; ++sub) {
        accr[sub] += __shfl_xor_sync(FULL, accr[sub], 1);
        acci[sub] += __shfl_xor_sync(FULL, acci[sub], 1);
    }

    // Route: point L's value lives in accr[L>>4] of lanes 2*(L&15), 2*(L&15)+1.
    const int srcl = 2 * (lane & 15);
    const float r0 = __shfl_sync(FULL, accr[0], srcl);
    const float i0 = __shfl_sync(FULL, acci[0], srcl);
    const float r1 = __shfl_sync(FULL, accr[1], srcl);
    const float i1 = __shfl_sync(FULL, acci[1], srcl);
    const float vr = ((lane < 16) ? r0 : r1) + br;
    const float vi = ((lane < 16) ? i0 : i1) + bi;

    if (q < PTS) {
        out[(size_t)b * PTS + q] = make_float2(vr, vi * simag);
    }
}

extern "C" void kernel_launch(void* const* d_in, const int* in_sizes, int n_in,
                              void* d_out, int out_size)
{
    // Identify inputs by element count — robust to metadata ordering.
    const void* p_input  = nullptr;  // 2048
    const void* p_rot    = nullptr;  // 2304
    const void* p_grid   = nullptr;  // 2,342,844
    const void* p_weight = nullptr;
    const void* p_bias   = nullptr;
    long long wcand[2] = {0, 0};
    const void* pcand[2] = {nullptr, nullptr};
    int ncand = 0;

    for (int i = 0; i < n_in; ++i) {
        const long long s = in_sizes[i];
        if      (s == BATCH * ISIZE)           p_input = d_in[i];
        else if (s == BATCH * 9)               p_rot   = d_in[i];
        else if (s == (long long)GRID_ELEMS)   p_grid  = d_in[i];
        else if (s == PTS * 2 || s == 1)       { /* grid2d_coord / max_r unused */ }
        else if (ncand < 2)                    { wcand[ncand] = s; pcand[ncand] = d_in[i]; ++ncand; }
    }
    long long nw = 0;
    if (ncand == 2) {
        if (wcand[0] > wcand[1]) { p_weight = pcand[0]; p_bias = pcand[1]; nw = wcand[1] / 2; }
        else                     { p_weight = pcand[1]; p_bias = pcand[0]; nw = wcand[0] / 2; }
    }
    if (nw > NWMAX) nw = NWMAX;

    const long long pthreads = nw * 4 + TABN;
    prep_kernel<<<(unsigned)((pthreads + 255) / 256), 256>>>(
        (const float4*)p_weight, (const float2*)p_bias, (const int*)p_grid, (int)nw);

    dim3 grid((PTS + 255) / 256, BATCH);
    svr_kernel<<<grid, 256>>>((const float*)p_input,
                              (const int*)p_grid,
                              (const float*)p_rot,
                              (float2*)d_out);
}

// round 17
// speedup vs baseline: 1.0856x; 1.0856x over previous
#include <cuda_runtime.h>
#include <cuda_fp16.h>

// SparseVolumeReconstructionLinear — GB300 sm_103a
#define BATCH   256
#define ISIZE   8
#define HW      80
#define PX      81
#define PTS     (161 * 81)      // 13041
#define BZM     167
#define BZ2     83
#define GX      84
#define GZSTRIDE (BZM * GX)     // 14028
#define GRID_ELEMS (BZM * BZM * GX)
#define MR2     6400
#define NWMAX   1250000
#define TABN    (BZM * BZM)     // 27889

// Scratch (allocation-free: __device__ globals).
__device__ __half2 g_wh[NWMAX * 8];   // fp16 weight rows, 32 B each
__device__ uint2   g_bp[NWMAX];       // bias pair {bh[j], bh[j+1]}, 8 B
__device__ uint2   g_tp[TABN];        // per (z,y): {packed(z,y), packed(z,y+1)}

__device__ __forceinline__ int grid_is64(const int* __restrict__ g)
{
    const int r = 83 * GZSTRIDE + 83 * GX;   // even interior offset
    return (__ldg(g + r + 1) == 0) ? 1 : 0;
}

__device__ __forceinline__ int tab_packed(const int* __restrict__ grid3d,
                                          int z, int y, int is64)
{
    const int zb = z - BZ2, yb = y - BZ2;
    const int rr = MR2 - zb * zb - yb * yb;
    if (rr < 0) return 0;
    int xm = (int)sqrtf((float)rr);
    while ((xm + 1) * (xm + 1) <= rr) ++xm;
    while (xm * xm > rr) --xm;
    const int lin0 = z * GZSTRIDE + y * GX;
    const int rs = __ldg(grid3d + (is64 ? 2 * lin0 : lin0));
    return (rs << 7) | (xm + 1);
}

// Prep: fp16 convert (4 thr/row) + bias pairs + table pairs.
// Source fp32 reads use __ldcs (evict-first) so the one-shot stream does not
// evict the hot fp16 tables the main kernel is about to gather from.
__global__ __launch_bounds__(256) void prep_kernel(
    const float4* __restrict__ w, const float2* __restrict__ bia,
    const int* __restrict__ grid3d, int nw)
{
    const long long t = (long long)blockIdx.x * 256 + threadIdx.x;
    const long long cvt_n = (long long)nw * 4;

    if (t < cvt_n) {
        const int r = (int)(t >> 2), part = (int)(t & 3);
        const float4 a = __ldcs(w + (size_t)r * 4 + part);
        const __half2 h0 = __floats2half2_rn(a.x, a.y);
        const __half2 h1 = __floats2half2_rn(a.z, a.w);
        uint2 v;
        v.x = *reinterpret_cast<const unsigned*>(&h0);
        v.y = *reinterpret_cast<const unsigned*>(&h1);
        *reinterpret_cast<uint2*>(&g_wh[(size_t)r * 8 + part * 2]) = v;
        if (part == 0) {
            const float2 b0 = __ldcs(bia + r);
            const __half2 hb0 = __floats2half2_rn(b0.x, b0.y);
            __half2 hb1 = __floats2half2_rn(0.f, 0.f);
            if (r + 1 < nw) {
                const float2 b1 = __ldcs(bia + r + 1);
                hb1 = __floats2half2_rn(b1.x, b1.y);
            }
            uint2 bp;
            bp.x = *reinterpret_cast<const unsigned*>(&hb0);
            bp.y = *reinterpret_cast<const unsigned*>(&hb1);
            g_bp[r] = bp;
        }
    } else if (t < cvt_n + TABN) {
        const int e = (int)(t - cvt_n);
        const int z = e / BZM, y = e % BZM;
        const int is64 = grid_is64(grid3d);
        uint2 tp;
        tp.x = (unsigned)tab_packed(grid3d, z, y, is64);
        tp.y = (y + 1 < BZM) ? (unsigned)tab_packed(grid3d, z, y + 1, is64) : 0u;
        g_tp[e] = tp;
    }
}

__global__ __launch_bounds__(256, 6) void svr_kernel(
    const float*  __restrict__ input,    // (256, 8)
    const int*    __restrict__ grid3d,   // int32 (or int64 LE)
    const float*  __restrict__ rot,      // (256, 3, 3)
    float2*       __restrict__ out)      // (256, 13041, 2)
{
    const int b    = blockIdx.y;
    const int q    = blockIdx.x * 256 + threadIdx.x;
    const int lane = threadIdx.x & 31;
    const unsigned FULL = 0xffffffffu;

    // ---- Owner role: 8 corner indices + weights (via dx-pair records) ------
    int   jc[8];
    float wt[8];
    float simag = 1.f;

    bool active = false;
    int  xi2 = 0, iy = 0;
    if (q < PTS) {
        xi2 = q % PX;                     // 0..80
        iy  = q / PX - HW;                // -80..80
        active = (xi2 * xi2 + iy * iy <= MR2);
    }

    // Whole-warp early exit: ~15% of warps are entirely outside the disc.
    if (__ballot_sync(FULL, active) == 0u) {
        if (q < PTS) out[(size_t)b * PTS + q] = make_float2(0.f, 0.f);
        return;
    }

    if (active) {
        const float* R = rot + b * 9;
        const float x = (float)xi2, y = (float)iy;
        float cx = R[0] * x + R[1] * y;
        float cy = R[3] * x + R[4] * y;
        float cz = R[6] * x + R[7] * y;
        if (cx < 0.f) { cx = -cx; cy = -cy; cz = -cz; simag = -1.f; }

        const float fx = floorf(cx), fy = floorf(cy), fz = floorf(cz);
        const int   ix = (int)fx,    iyc = (int)fy,   iz = (int)fz;
        const float tx = cx - fx,    ty = cy - fy,    tz = cz - fz;

        const float wxl0 = 1.f - tx, wxl1 = tx;
        const float wyl[2] = {1.f - ty, ty};
        const float wzl[2] = {1.f - tz, tz};

        const int is64 = grid_is64(grid3d);
        #pragma unroll
        for (int dz = 0; dz < 2; ++dz) {
            const int zc  = iz + dz + BZ2;
            const int yc0 = iyc + BZ2;
            const uint2 tp = __ldg(g_tp + zc * BZM + yc0);
            #pragma unroll
            for (int dy = 0; dy < 2; ++dy) {
                const int cc  = dz * 4 + dy * 2;        // jc slots cc, cc+1
                const int yc  = yc0 + dy;
                const int ent = (int)(dy ? tp.y : tp.x);
                const int xm1 = ent & 127;
                const int rs  = ent >> 7;
                int jj0, jj1;
                if (ix + 1 < xm1) {               // both corners in-ball
                    jj0 = rs + ix;
                    jj1 = jj0 + 1;
                } else {                          // rare: edge / margin / expansion
                    const int lin = zc * GZSTRIDE + yc * GX + ix;
                    if (ix < xm1) jj0 = rs + ix;
                    else jj0 = __ldg(grid3d + (is64 ? 2 * lin : lin));
                    jj1 = __ldg(grid3d + (is64 ? 2 * (lin + 1) : lin + 1));
                }
                jc[cc]     = jj0;
                jc[cc + 1] = jj1;
                const float wzy = wzl[dz] * wyl[dy];
                wt[cc]     = wzy * wxl0;
                wt[cc + 1] = wzy * wxl1;
            }
        }
    } else {
        #pragma unroll
        for (int c = 0; c < 8; ++c) { jc[c] = -1; wt[c] = 0.f; }
    }

    // Owner-side bias (paired LDG.64 on the common path; fallback via g_bp.x).
    float br = 0.f, bi = 0.f;
    #pragma unroll
    for (int c = 0; c < 8; c += 2) {
        const int jj0 = jc[c], jj1 = jc[c + 1];
        if (jj0 >= 0 && jj1 == jj0 + 1) {
            const uint2 bp = __ldg(g_bp + jj0);
            const float2 b0 = __half22float2(*reinterpret_cast<const __half2*>(&bp.x));
            const float2 b1 = __half22float2(*reinterpret_cast<const __half2*>(&bp.y));
            br += wt[c] * b0.x + wt[c + 1] * b1.x;
            bi += wt[c] * b0.y + wt[c + 1] * b1.y;
        } else {
            if (jj0 >= 0) {
                const uint2 bp = __ldg(g_bp + jj0);
                const float2 b0 = __half22float2(*reinterpret_cast<const __half2*>(&bp.x));
                br += wt[c] * b0.x; bi += wt[c] * b0.y;
            }
            if (jj1 >= 0) {
                const uint2 bp = __ldg(g_bp + jj1);
                const float2 b1 = __half22float2(*reinterpret_cast<const __half2*>(&bp.x));
                br += wt[c + 1] * b1.x; bi += wt[c + 1] * b1.y;
            }
        }
    }

    // ---- Team role: 2 lanes/row (slot = feature half), 16 rows per LDG.128 -
    const float4 fv = __ldg(reinterpret_cast<const float4*>(input + b * ISIZE) + (lane & 1));
    __half2 fh0 = __floats2half2_rn(fv.x, fv.x);
    __half2 fh1 = __floats2half2_rn(fv.y, fv.y);
    __half2 fh2 = __floats2half2_rn(fv.z, fv.z);
    __half2 fh3 = __floats2half2_rn(fv.w, fv.w);
    const int slot = lane & 1;
    const int rsel = lane >> 1;                // 0..15

    const uint4* wh = reinterpret_cast<const uint4*>(g_wh);  // 2 uint4 per row

    // Phase 1: hoist ALL (j, w) shuffles before any weight load.
    int   jrr[16];
    float wrr[16];
    #pragma unroll
    for (int c = 0; c < 8; ++c) {
        #pragma unroll
        for (int sub = 0; sub < 2; ++sub) {
            const int k   = c * 2 + sub;
            const int src = sub * 16 + rsel;
            const int   jr = __shfl_sync(FULL, jc[c], src);
            const float wr = __shfl_sync(FULL, wt[c], src);
            wrr[k] = (jr >= 0) ? wr : 0.f;     // invalid corner contributes 0
            jrr[k] = (jr >= 0) ? jr : 0;       // safe row for unconditional load
        }
    }

    // Phase 2: 16 unconditional LDG.128 + HFMA2 dot, fully unrolled (high MLP).
    float accr[2] = {0.f, 0.f};
    float acci[2] = {0.f, 0.f};
    #pragma unroll
    for (int k = 0; k < 16; ++k) {
        const uint4 wv = __ldg(wh + (size_t)jrr[k] * 2 + slot);
        const __half2* hp = reinterpret_cast<const __half2*>(&wv);
        __half2 acc = __hmul2(fh0, hp[0]);
        acc = __hfma2(fh1, hp[1], acc);
        acc = __hfma2(fh2, hp[2], acc);
        acc = __hfma2(fh3, hp[3], acc);
        const float2 d = __half22float2(acc);
        accr[k & 1] += wrr[k] * d.x;
        acci[k & 1] += wrr[k] * d.y;
    }

    // Reduce each sub over its lane pair (feature halves).
    #pragma unroll
    for (int sub = 0; sub < 2; ++sub) {
        accr[sub] += __shfl_xor_sync(FULL, accr[sub], 1);
        acci[sub] += __shfl_xor_sync(FULL, acci[sub], 1);
    }

    // Route: point L's value lives in accr[L>>4] of lanes 2*(L&15), 2*(L&15)+1.
    const int srcl = 2 * (lane & 15);
    const float r0 = __shfl_sync(FULL, accr[0], srcl);
    const float i0 = __shfl_sync(FULL, acci[0], srcl);
    const float r1 = __shfl_sync(FULL, accr[1], srcl);
    const float i1 = __shfl_sync(FULL, acci[1], srcl);
    const float vr = ((lane < 16) ? r0 : r1) + br;
    const float vi = ((lane < 16) ? i0 : i1) + bi;

    if (q < PTS) {
        out[(size_t)b * PTS + q] = make_float2(vr, vi * simag);
    }
}

extern "C" void kernel_launch(void* const* d_in, const int* in_sizes, int n_in,
                              void* d_out, int out_size)
{
    // Identify inputs by element count — robust to metadata ordering.
    const void* p_input  = nullptr;  // 2048
    const void* p_rot    = nullptr;  // 2304
    const void* p_grid   = nullptr;  // 2,342,844
    const void* p_weight = nullptr;
    const void* p_bias   = nullptr;
    long long wcand[2] = {0, 0};
    const void* pcand[2] = {nullptr, nullptr};
    int ncand = 0;

    for (int i = 0; i < n_in; ++i) {
        const long long s = in_sizes[i];
        if      (s == BATCH * ISIZE)           p_input = d_in[i];
        else if (s == BATCH * 9)               p_rot   = d_in[i];
        else if (s == (long long)GRID_ELEMS)   p_grid  = d_in[i];
        else if (s == PTS * 2 || s == 1)       { /* grid2d_coord / max_r unused */ }
        else if (ncand < 2)                    { wcand[ncand] = s; pcand[ncand] = d_in[i]; ++ncand; }
    }
    long long nw = 0;
    if (ncand == 2) {
        if (wcand[0] > wcand[1]) { p_weight = pcand[0]; p_bias = pcand[1]; nw = wcand[1] / 2; }
        else                     { p_weight = pcand[1]; p_bias = pcand[0]; nw = wcand[0] / 2; }
    }
    if (nw > NWMAX) nw = NWMAX;

    const long long pthreads = nw * 4 + TABN;
    prep_kernel<<<(unsigned)((pthreads + 255) / 256), 256>>>(
        (const float4*)p_weight, (const float2*)p_bias, (const int*)p_grid, (int)nw);

    dim3 grid((PTS + 255) / 256, BATCH);
    svr_kernel<<<grid, 256>>>((const float*)p_input,
                              (const int*)p_grid,
                              (const float*)p_rot,
                              (float2*)d_out);
}